// round 6
// baseline (speedup 1.0000x reference)
#include <cuda_runtime.h>
#include <cstdint>
#include <cstddef>

// Problem constants (fixed shapes from reference):
//   x:   (B=32, D=256, H=32, W=32) fp32
//   emb: (D=256, K=2048) fp32
//   out: (32, 256, 32, 32) fp32 = nearest code per latent
#define DDIM     256
#define KCODES   2048
#define SPATIAL  1024        // H*W per batch
#define BM       128         // latent rows per block tile
#define BKT      128         // codes per k-tile
#define DCH      16          // d-depth per smem chunk
#define NTHREADS 256
#define NCHUNKS  ((KCODES / BKT) * (DDIM / DCH))   // 256

// smem per buffer: Xdup 16x256 floats (4096) + E 16x128 floats (2048) = 6144
#define XBUF     6144
#define EOFF     4096

// Scratch: 0.5*||e_k||^2 per code (device global: no allocs allowed).
__device__ float g_cnorm[KCODES];

// ---------------------------------------------------------------------------
// Kernel 1: cnorm[k] = 0.5 * sum_d emb[d][k]^2
// ---------------------------------------------------------------------------
__global__ void cnorm_kernel(const float* __restrict__ emb) {
    int k = blockIdx.x * blockDim.x + threadIdx.x;
    float s = 0.0f;
#pragma unroll 8
    for (int d = 0; d < DDIM; ++d) {
        float e = emb[d * KCODES + k];
        s = fmaf(e, e, s);
    }
    g_cnorm[k] = 0.5f * s;
}

// ---------------------------------------------------------------------------
// Packed fp32x2 helpers (Blackwell sm_100+: fma.rn.f32x2 — PTX-only path)
// ---------------------------------------------------------------------------
__device__ __forceinline__ void unpack2(unsigned long long v, float& lo, float& hi) {
    asm("mov.b64 {%0, %1}, %2;" : "=f"(lo), "=f"(hi) : "l"(v));
}
__device__ __forceinline__ void fma2(unsigned long long& d,
                                     unsigned long long a,
                                     unsigned long long b) {
    asm("fma.rn.f32x2 %0, %1, %2, %0;" : "+l"(d) : "l"(a), "l"(b));
}
// LDS.128 as two packed b64 values.
__device__ __forceinline__ void lds_b64x2(const float* p,
                                          unsigned long long& a,
                                          unsigned long long& b) {
    unsigned sa = (unsigned)__cvta_generic_to_shared((const void*)p);
    asm volatile("ld.shared.v2.b64 {%0, %1}, [%2];" : "=l"(a), "=l"(b) : "r"(sa));
}

// ---------------------------------------------------------------------------
// Kernel 2: fused distance-GEMM + argmin + code gather.
// Grid: 256 blocks (N/BM). Block: 256 threads (16x16), 8x8 microtile.
//   X staged DUPLICATED: Xdup[dd][2r]=Xdup[dd][2r+1]=x[r]  -> a-operand is a
//     direct conflict-free (broadcast) ld.shared.v2.b64.
//   Codes per thread: k = kt*128 + tx*4 + 64*j + {0..3}  -> E loads are
//     2x LDS.128/dd, 16B stride across tx: conflict-free.
// Per dd-step: 6 LDS.128 + 32 FFMA2 (84% fma mix, no ALU in operand path).
// ---------------------------------------------------------------------------
__global__ void __launch_bounds__(NTHREADS, 2)
nearest_main(const float* __restrict__ x, const float* __restrict__ emb,
             float* __restrict__ out) {
    __shared__ __align__(16) float smem[2 * XBUF];   // 48 KB

    const int t   = threadIdx.x;
    const int tx  = t & 15;        // column-group (codes)
    const int ty  = t >> 4;        // row-group (latents)
    const int bid = blockIdx.x;
    const int b   = bid >> 3;              // batch
    const int s0  = (bid & 7) * BM;        // spatial offset within batch
    const float* xb = x + (size_t)b * (DDIM * SPATIAL) + s0;

    // Loader mapping: each thread moves 2 float4 per operand per chunk.
    const int dd0 = t >> 5;            // 0..7
    const int i0  = (t & 31) * 4;      // 0..124
    const int dd1 = dd0 + 8;           // 8..15

    float4 px0, px1, pe0, pe1;

    // Prefetch chunk 0 (kt=0, dc=0).
    px0 = *(const float4*)(xb + dd0 * SPATIAL + i0);
    px1 = *(const float4*)(xb + dd1 * SPATIAL + i0);
    pe0 = *(const float4*)(emb + dd0 * KCODES + i0);
    pe1 = *(const float4*)(emb + dd1 * KCODES + i0);

    float best[8];
    int   bestk[8];
#pragma unroll
    for (int r = 0; r < 8; ++r) { best[r] = 3.4e38f; bestk[r] = 0; }

    for (int kt = 0; kt < KCODES / BKT; ++kt) {
        unsigned long long acc[8][4];
#pragma unroll
        for (int r = 0; r < 8; ++r)
#pragma unroll
            for (int j = 0; j < 4; ++j) acc[r][j] = 0ull;

        for (int dc = 0; dc < DDIM / DCH; ++dc) {
            const int c = (kt << 4) + dc;
            float* Xd = smem + (c & 1) * XBUF;
            float* Eb = Xd + EOFF;

            // Stage chunk c: X duplicated, E linear.
            {
                float4 d0a = make_float4(px0.x, px0.x, px0.y, px0.y);
                float4 d0b = make_float4(px0.z, px0.z, px0.w, px0.w);
                float4 d1a = make_float4(px1.x, px1.x, px1.y, px1.y);
                float4 d1b = make_float4(px1.z, px1.z, px1.w, px1.w);
                *(float4*)(Xd + dd0 * 256 + 2 * i0)     = d0a;
                *(float4*)(Xd + dd0 * 256 + 2 * i0 + 4) = d0b;
                *(float4*)(Xd + dd1 * 256 + 2 * i0)     = d1a;
                *(float4*)(Xd + dd1 * 256 + 2 * i0 + 4) = d1b;
                *(float4*)(Eb + dd0 * BKT + i0) = pe0;
                *(float4*)(Eb + dd1 * BKT + i0) = pe1;
            }
            __syncthreads();

            // Prefetch chunk c+1 into registers (overlaps with compute below).
            if (c + 1 < NCHUNKS) {
                const int cn    = c + 1;
                const int ktn   = cn >> 4;
                const int dbase = (cn & 15) * DCH;
                px0 = *(const float4*)(xb + (dbase + dd0) * SPATIAL + i0);
                px1 = *(const float4*)(xb + (dbase + dd1) * SPATIAL + i0);
                const float* eb = emb + ktn * BKT;
                pe0 = *(const float4*)(eb + (dbase + dd0) * KCODES + i0);
                pe1 = *(const float4*)(eb + (dbase + dd1) * KCODES + i0);
            }

            const float* Xrow = Xd + ty * 16;  // 8 rows, duplicated
            const float* Erow = Eb + tx * 4;   // 4 consecutive codes
#pragma unroll
            for (int dd = 0; dd < DCH; ++dd) {
                unsigned long long a2[8], b2[4];
                lds_b64x2(Xrow + dd * 256 + 0,  a2[0], a2[1]);
                lds_b64x2(Xrow + dd * 256 + 4,  a2[2], a2[3]);
                lds_b64x2(Xrow + dd * 256 + 8,  a2[4], a2[5]);
                lds_b64x2(Xrow + dd * 256 + 12, a2[6], a2[7]);
                lds_b64x2(Erow + dd * BKT + 0,  b2[0], b2[1]);
                lds_b64x2(Erow + dd * BKT + 64, b2[2], b2[3]);
#pragma unroll
                for (int r = 0; r < 8; ++r)
#pragma unroll
                    for (int j = 0; j < 4; ++j) fma2(acc[r][j], a2[r], b2[j]);
            }
        }

        // k-tile epilogue: v = 0.5*||e||^2 - x.e ; running min.
        // Thread's codes: kbase + {0,1,2,3, 64,65,66,67} (ascending across
        // j then within pair), so strict '<' keeps the earliest k in-thread.
        const int kbase = kt * BKT + tx * 4;
        const int koff[4] = {0, 2, 64, 66};
        float cv[8];
#pragma unroll
        for (int j = 0; j < 4; ++j) {
            cv[2 * j]     = __ldg(&g_cnorm[kbase + koff[j]]);
            cv[2 * j + 1] = __ldg(&g_cnorm[kbase + koff[j] + 1]);
        }
#pragma unroll
        for (int r = 0; r < 8; ++r) {
#pragma unroll
            for (int j = 0; j < 4; ++j) {
                float d0, d1;
                unpack2(acc[r][j], d0, d1);
                float v0 = cv[2 * j]     - d0;
                float v1 = cv[2 * j + 1] - d1;
                if (v0 < best[r]) { best[r] = v0; bestk[r] = kbase + koff[j]; }
                if (v1 < best[r]) { best[r] = v1; bestk[r] = kbase + koff[j] + 1; }
            }
        }
    }

    // Cross-thread reduction: 16 tx-threads share each row. Reuse tile smem.
    __syncthreads();
    float* rv = smem;                    // [16][128]
    int*   ri = (int*)(smem + 2048);     // [16][128]
    int*   km = (int*)(smem + 4096);     // [128]
#pragma unroll
    for (int r = 0; r < 8; ++r) {
        rv[tx * BM + ty * 8 + r] = best[r];
        ri[tx * BM + ty * 8 + r] = bestk[r];
    }
    __syncthreads();
    if (t < BM) {
        float bv = rv[t];
        int   bk = ri[t];
#pragma unroll
        for (int i = 1; i < 16; ++i) {
            float v  = rv[i * BM + t];
            int   kk = ri[i * BM + t];
            if (v < bv || (v == bv && kk < bk)) { bv = v; bk = kk; }
        }
        km[t] = bk;
    }
    __syncthreads();

    // Gather winning codes: out[b, d, s0+r] = emb[d, km[r]].
    float* ob = out + (size_t)b * (DDIM * SPATIAL) + s0;
    for (int idx = t; idx < BM * DDIM; idx += NTHREADS) {
        const int r = idx & (BM - 1);
        const int d = idx >> 7;
        ob[d * SPATIAL + r] = __ldg(&emb[d * KCODES + km[r]]);
    }
}

// ---------------------------------------------------------------------------
extern "C" void kernel_launch(void* const* d_in, const int* in_sizes, int n_in,
                              void* d_out, int out_size) {
    const float* x   = (const float*)d_in[0];
    const float* emb = (const float*)d_in[1];
    // Defensive: x (8.4M elems) is larger than emb (0.5M elems).
    if (n_in >= 2 && in_sizes[0] < in_sizes[1]) {
        emb = (const float*)d_in[0];
        x   = (const float*)d_in[1];
    }
    float* out = (float*)d_out;

    cnorm_kernel<<<KCODES / 256, 256>>>(emb);
    nearest_main<<<(32 * SPATIAL) / BM, NTHREADS>>>(x, emb, out);
}

// round 8
// speedup vs baseline: 1.3006x; 1.3006x over previous
#include <cuda_runtime.h>
#include <cuda_bf16.h>
#include <cstdint>
#include <cstddef>

// Shapes: x (32,256,32,32) fp32, emb (256,2048) fp32, out = nearest codes.
#define DDIM     256
#define KCODES   2048
#define SPATIAL  1024
#define BM       128                 // rows per CTA
#define THREADS  256
#define ABYTES   65536               // one A split: 128 rows x 256 bf16 (512B/row)
#define BCHUNK   16384               // B chunk: 128 codes x 64 bf16 (128B/row)
#define DSMEM    (3 * ABYTES + BCHUNK)   // 212992

// Device scratch (no allocs allowed).
__device__ float g_cnorm[KCODES];
__device__ __align__(16) __nv_bfloat16 g_bsplit[3][KCODES * DDIM];  // [split][k*256+d]

// ---------------------------------------------------------------------------
// Prep 1: cnorm[k] = 0.5 * sum_d emb[d][k]^2  (fp32)
// ---------------------------------------------------------------------------
__global__ void cnorm_kernel(const float* __restrict__ emb) {
    int k = blockIdx.x * blockDim.x + threadIdx.x;
    float s = 0.0f;
#pragma unroll 8
    for (int d = 0; d < DDIM; ++d) { float e = emb[d * KCODES + k]; s = fmaf(e, e, s); }
    g_cnorm[k] = 0.5f * s;
}

// ---------------------------------------------------------------------------
// Prep 2: 3-way bf16 split of emb, transposed to [k][d].
// ---------------------------------------------------------------------------
__global__ void bsplit_kernel(const float* __restrict__ emb) {
    int idx = blockIdx.x * blockDim.x + threadIdx.x;   // k*256 + d
    int k = idx >> 8, d = idx & 255;
    float v = emb[d * KCODES + k];
    __nv_bfloat16 a = __float2bfloat16(v);
    float r1 = v - __bfloat162float(a);
    __nv_bfloat16 b = __float2bfloat16(r1);
    float r2 = r1 - __bfloat162float(b);
    __nv_bfloat16 c = __float2bfloat16(r2);
    g_bsplit[0][idx] = a; g_bsplit[1][idx] = b; g_bsplit[2][idx] = c;
}

// ---------------------------------------------------------------------------
// Helpers: sm_80-compatible mma.sync (compiles for compute_103, no 'a' needed)
// ---------------------------------------------------------------------------
__device__ __forceinline__ uint32_t lds32(uint32_t a) {
    uint32_t r; asm volatile("ld.shared.b32 %0, [%1];" : "=r"(r) : "r"(a)); return r;
}
__device__ __forceinline__ void sts128(uint32_t a, uint4 v) {
    asm volatile("st.shared.v4.b32 [%0], {%1,%2,%3,%4};"
                 :: "r"(a), "r"(v.x), "r"(v.y), "r"(v.z), "r"(v.w));
}
__device__ __forceinline__ void mma16816(float* c, uint32_t a0, uint32_t a1,
                                         uint32_t a2, uint32_t a3,
                                         uint32_t b0, uint32_t b1) {
    asm volatile(
        "mma.sync.aligned.m16n8k16.row.col.f32.bf16.bf16.f32 "
        "{%0,%1,%2,%3}, {%4,%5,%6,%7}, {%8,%9}, {%0,%1,%2,%3};"
        : "+f"(c[0]), "+f"(c[1]), "+f"(c[2]), "+f"(c[3])
        : "r"(a0), "r"(a1), "r"(a2), "r"(a3), "r"(b0), "r"(b1));
}

// ---------------------------------------------------------------------------
// Main: 1 CTA = 128 rows vs all 2048 codes, 6-pass bf16-split HMMA GEMM
// fused with exact running argmin.
//   A: 3 splits in smem, layout A[r][k]: byte = r*512 + ((2k) ^ ((r&7)<<4)).
//   B: streamed 16KB chunks (128 codes x 64 k), byte = n*128 + (c ^ ((n&7)<<4)).
//   Pass grouping by B split s: A splits t = 0..(2-s)  (covers all t+s<=2).
//   Warp (wm, wn): rows wm*32..+31, codes wn*64..+63 of each 128-code n-tile.
// ---------------------------------------------------------------------------
__global__ void __launch_bounds__(THREADS, 1)
nearest_hmma(const float* __restrict__ x, const float* __restrict__ emb,
             float* __restrict__ out) {
    extern __shared__ __align__(16) unsigned char sm[];
    unsigned char* Asm = sm;
    __shared__ float s_rv[2][BM];
    __shared__ int   s_rk[2][BM];
    __shared__ int   s_km[BM];

    const int t    = threadIdx.x;
    const int lane = t & 31, warp = t >> 5;
    const int g    = lane >> 2, q = lane & 3;     // fragment row-group / quad
    const int wm   = warp & 3,  wn = warp >> 2;
    const int b    = blockIdx.x >> 3;
    const int s0   = (blockIdx.x & 7) * BM;

    const uint32_t A_u = (uint32_t)__cvta_generic_to_shared(Asm);
    const uint32_t B_u = A_u + 3 * ABYTES;

    // ---- Stage A: 3-way bf16 split of the x-tile into swizzled smem ----
    const float* xb = x + ((size_t)b * DDIM) * SPATIAL + s0;
    {
        const int i = t & 127, dp = t >> 7;
#pragma unroll 4
        for (int it = 0; it < 128; ++it) {
            const int d = it * 2 + dp;
            float v = xb[(size_t)d * SPATIAL + i];
            __nv_bfloat16 pa = __float2bfloat16(v);
            float r1 = v - __bfloat162float(pa);
            __nv_bfloat16 pb = __float2bfloat16(r1);
            float r2 = r1 - __bfloat162float(pb);
            __nv_bfloat16 pc = __float2bfloat16(r2);
            uint32_t off = (uint32_t)i * 512u
                         + (((uint32_t)d * 2u) ^ (((uint32_t)(i & 7)) << 4));
            *(__nv_bfloat16*)(Asm + off)              = pa;
            *(__nv_bfloat16*)(Asm + ABYTES + off)     = pb;
            *(__nv_bfloat16*)(Asm + 2 * ABYTES + off) = pc;
        }
    }

    // ---- Prefetch B chunk 0 (nt=0, s=0, kc=0) into registers ----
    const int np = t >> 1, h = t & 1;        // staging: row np, 64B half h
    uint4 pf0, pf1, pf2, pf3;
    {
        const uint4* src = (const uint4*)(g_bsplit[0] + ((size_t)np * 256 + h * 32));
        pf0 = src[0]; pf1 = src[1]; pf2 = src[2]; pf3 = src[3];
    }
    __syncthreads();

    const uint32_t xorv = (uint32_t)g << 4;
    const uint32_t raA[2] = { (uint32_t)(wm * 32 + g) * 512u,
                              (uint32_t)(wm * 32 + 16 + g) * 512u };
    const uint32_t bnb = B_u + (uint32_t)(wn * 64 + g) * 128u;
    const uint32_t bst_base = B_u + (uint32_t)np * 128u;
    const uint32_t bst_xor  = ((uint32_t)(np & 7)) << 4;

    float bv[2][2]; int bk[2][2];
#pragma unroll
    for (int mt = 0; mt < 2; ++mt)
#pragma unroll
        for (int hi = 0; hi < 2; ++hi) { bv[mt][hi] = 3.4e38f; bk[mt][hi] = 0; }

    for (int nt = 0; nt < KCODES / 128; ++nt) {
        float acc[2][8][4];
#pragma unroll
        for (int mt = 0; mt < 2; ++mt)
#pragma unroll
            for (int j = 0; j < 8; ++j)
#pragma unroll
                for (int cc = 0; cc < 4; ++cc) acc[mt][j][cc] = 0.0f;

        for (int ci = 0; ci < 12; ++ci) {           // (s, kc): s=ci>>2, kc=ci&3
            const int s  = ci >> 2;
            const int kc = ci & 3;

            __syncthreads();                         // prior chunk fully consumed
            {   // store prefetched chunk (16B stores, conflict-free per phase)
                uint32_t c0 = (uint32_t)h * 64u;
                sts128(bst_base + ((c0 +  0u) ^ bst_xor), pf0);
                sts128(bst_base + ((c0 + 16u) ^ bst_xor), pf1);
                sts128(bst_base + ((c0 + 32u) ^ bst_xor), pf2);
                sts128(bst_base + ((c0 + 48u) ^ bst_xor), pf3);
            }
            __syncthreads();                         // chunk visible

            {   // prefetch next chunk (overlaps the mma loop below)
                int nc = nt * 12 + ci + 1;
                if (nc < 192) {
                    int nnt = nc / 12, rem = nc % 12;
                    const uint4* src = (const uint4*)(g_bsplit[rem >> 2] +
                        ((size_t)(nnt * 128 + np) * 256 + (rem & 3) * 64 + h * 32));
                    pf0 = src[0]; pf1 = src[1]; pf2 = src[2]; pf3 = src[3];
                }
            }

            const int npass = 3 - s;                 // A splits paired with this B split
            const uint32_t kcol = (uint32_t)kc * 128u;
#pragma unroll
            for (int ks = 0; ks < 4; ++ks) {
                const uint32_t cl0 = (((uint32_t)ks * 32u + (uint32_t)q * 4u) ^ xorv);
                const uint32_t cl1 = (((uint32_t)ks * 32u + (uint32_t)q * 4u + 16u) ^ xorv);
                uint32_t b0[8], b1[8];
#pragma unroll
                for (int j = 0; j < 8; ++j) {
                    b0[j] = lds32(bnb + (uint32_t)j * 1024u + cl0);
                    b1[j] = lds32(bnb + (uint32_t)j * 1024u + cl1);
                }
                for (int ts = 0; ts < npass; ++ts) {
                    const uint32_t ab = A_u + (uint32_t)ts * ABYTES + kcol;
#pragma unroll
                    for (int mt = 0; mt < 2; ++mt) {
                        uint32_t a0 = lds32(ab + raA[mt] + cl0);
                        uint32_t a1 = lds32(ab + raA[mt] + 4096u + cl0);
                        uint32_t a2 = lds32(ab + raA[mt] + cl1);
                        uint32_t a3 = lds32(ab + raA[mt] + 4096u + cl1);
#pragma unroll
                        for (int j = 0; j < 8; ++j)
                            mma16816(acc[mt][j], a0, a1, a2, a3, b0[j], b1[j]);
                    }
                }
            }
        }

        // ---- n-tile epilogue: score = 0.5||e||^2 - x.e, running argmin ----
        const int kb = nt * 128 + wn * 64 + q * 2;
        float cn[16];
#pragma unroll
        for (int j = 0; j < 8; ++j) {
            cn[2 * j]     = __ldg(&g_cnorm[kb + 8 * j]);
            cn[2 * j + 1] = __ldg(&g_cnorm[kb + 8 * j + 1]);
        }
#pragma unroll
        for (int mt = 0; mt < 2; ++mt)
#pragma unroll
            for (int hi = 0; hi < 2; ++hi)
#pragma unroll
                for (int j = 0; j < 8; ++j)
#pragma unroll
                    for (int par = 0; par < 2; ++par) {
                        float v = cn[2 * j + par] - acc[mt][j][hi * 2 + par];
                        int   k = kb + 8 * j + par;
                        if (v < bv[mt][hi]) { bv[mt][hi] = v; bk[mt][hi] = k; }
                    }
    }

    // ---- Reduce: 4 lanes (q) share each row; then wn halves; tie -> low k ----
#pragma unroll
    for (int mt = 0; mt < 2; ++mt)
#pragma unroll
        for (int hi = 0; hi < 2; ++hi) {
            float v = bv[mt][hi]; int k = bk[mt][hi];
#pragma unroll
            for (int d = 1; d <= 2; d <<= 1) {
                float vo = __shfl_xor_sync(0xffffffffu, v, d);
                int   ko = __shfl_xor_sync(0xffffffffu, k, d);
                if (vo < v || (vo == v && ko < k)) { v = vo; k = ko; }
            }
            if (q == 0) {
                int row = wm * 32 + mt * 16 + hi * 8 + g;
                s_rv[wn][row] = v; s_rk[wn][row] = k;
            }
        }
    __syncthreads();
    if (t < BM) {
        float v0 = s_rv[0][t]; int k0 = s_rk[0][t];
        float v1 = s_rv[1][t]; int k1 = s_rk[1][t];
        s_km[t] = (v1 < v0 || (v1 == v0 && k1 < k0)) ? k1 : k0;
    }
    __syncthreads();

    // ---- Gather winning codes: out[b, d, s0+r] = emb[d, km[r]] ----
    float* ob = out + ((size_t)b * DDIM) * SPATIAL + s0;
    for (int idx = t; idx < BM * DDIM; idx += THREADS) {
        const int r = idx & (BM - 1);
        const int d = idx >> 7;
        ob[(size_t)d * SPATIAL + r] = __ldg(&emb[d * KCODES + s_km[r]]);
    }
}

// ---------------------------------------------------------------------------
extern "C" void kernel_launch(void* const* d_in, const int* in_sizes, int n_in,
                              void* d_out, int out_size) {
    const float* x   = (const float*)d_in[0];
    const float* emb = (const float*)d_in[1];
    if (n_in >= 2 && in_sizes[0] < in_sizes[1]) {   // defensive order check
        emb = (const float*)d_in[0];
        x   = (const float*)d_in[1];
    }
    float* out = (float*)d_out;

    // Unconditional (no static guards): deterministic, not a stream op.
    cudaFuncSetAttribute(nearest_hmma, cudaFuncAttributeMaxDynamicSharedMemorySize,
                         DSMEM);

    cnorm_kernel<<<KCODES / 256, 256>>>(emb);
    bsplit_kernel<<<(KCODES * DDIM) / 256, 256>>>(emb);
    nearest_hmma<<<(32 * SPATIAL) / BM, THREADS, DSMEM>>>(x, emb, out);
}

// round 9
// speedup vs baseline: 2.4408x; 1.8767x over previous
#include <cuda_runtime.h>
#include <cuda_fp16.h>
#include <cstdint>
#include <cstddef>

// Shapes: x (32,256,32,32) fp32, emb (256,2048) fp32, out = nearest codes.
#define DDIM     256
#define KCODES   2048
#define SPATIAL  1024
#define BM       128                 // rows per CTA
#define THREADS  256
#define ABYTES   65536               // one A split: 128 rows x 256 fp16
#define BCHUNK   16384               // B chunk: 128 codes x 64 fp16
#define DSMEM    (2 * ABYTES + 2 * BCHUNK)   // 163840
#define NCHUNK   128                 // 16 n-tiles x 8 chunks

// Device scratch (no allocs allowed).
__device__ float g_cnorm[KCODES];
__device__ float g_cpart[8][KCODES];
__device__ __align__(16) __half g_bsplit2[2][KCODES * DDIM];  // [split][k*256+d]

// ---------------------------------------------------------------------------
// Prep: cnorm[k] = 0.5 * sum_d emb[d][k]^2  (8-way d-parallel + combine)
// ---------------------------------------------------------------------------
__global__ void cnorm_part(const float* __restrict__ emb) {
    const int dseg = blockIdx.x >> 3;
    const int k    = (blockIdx.x & 7) * 256 + threadIdx.x;
    float s = 0.0f;
#pragma unroll
    for (int dd = 0; dd < 32; ++dd) {
        float e = emb[(dseg * 32 + dd) * KCODES + k];
        s = fmaf(e, e, s);
    }
    g_cpart[dseg][k] = s;
}
__global__ void cnorm_combine() {
    const int k = blockIdx.x * 256 + threadIdx.x;
    float s = 0.0f;
#pragma unroll
    for (int i = 0; i < 8; ++i) s += g_cpart[i][k];
    g_cnorm[k] = 0.5f * s;
}

// ---------------------------------------------------------------------------
// Prep: 2-way fp16 split of emb, transposed to [k][d] via smem tile.
// ---------------------------------------------------------------------------
__global__ void bsplit2_kernel(const float* __restrict__ emb) {
    __shared__ float tile[32][33];
    const int kt0 = (blockIdx.x & 63) * 32;
    const int dt0 = (blockIdx.x >> 6) * 32;
    const int tx = threadIdx.x, ty = threadIdx.y;
#pragma unroll
    for (int i = 0; i < 4; ++i)
        tile[ty + 8 * i][tx] = emb[(size_t)(dt0 + ty + 8 * i) * KCODES + kt0 + tx];
    __syncthreads();
#pragma unroll
    for (int i = 0; i < 4; ++i) {
        const int k = kt0 + ty + 8 * i;
        const int d = dt0 + tx;
        float v = tile[tx][ty + 8 * i];
        __half hh = __float2half_rn(v);
        __half ll = __float2half_rn(v - __half2float(hh));
        g_bsplit2[0][(size_t)k * DDIM + d] = hh;
        g_bsplit2[1][(size_t)k * DDIM + d] = ll;
    }
}

// ---------------------------------------------------------------------------
// PTX helpers (all baseline features: sm_75/sm_80, compile for compute_103)
// ---------------------------------------------------------------------------
__device__ __forceinline__ void ldsm4(uint32_t& r0, uint32_t& r1, uint32_t& r2,
                                      uint32_t& r3, uint32_t addr) {
    asm volatile("ldmatrix.sync.aligned.m8n8.x4.shared.b16 {%0,%1,%2,%3}, [%4];"
                 : "=r"(r0), "=r"(r1), "=r"(r2), "=r"(r3) : "r"(addr));
}
__device__ __forceinline__ void mma16816(float* c, uint32_t a0, uint32_t a1,
                                         uint32_t a2, uint32_t a3,
                                         uint32_t b0, uint32_t b1) {
    asm volatile(
        "mma.sync.aligned.m16n8k16.row.col.f32.f16.f16.f32 "
        "{%0,%1,%2,%3}, {%4,%5,%6,%7}, {%8,%9}, {%0,%1,%2,%3};"
        : "+f"(c[0]), "+f"(c[1]), "+f"(c[2]), "+f"(c[3])
        : "r"(a0), "r"(a1), "r"(a2), "r"(a3), "r"(b0), "r"(b1));
}
__device__ __forceinline__ void cp16(uint32_t dst, const void* src) {
    asm volatile("cp.async.cg.shared.global [%0], [%1], 16;"
                 :: "r"(dst), "l"(src) : "memory");
}
__device__ __forceinline__ void cp_commit() {
    asm volatile("cp.async.commit_group;" ::: "memory");
}
__device__ __forceinline__ void cp_wait0() {
    asm volatile("cp.async.wait_group 0;" ::: "memory");
}

// Stage B chunk c into smem buffer (c&1). Chunk c: nt=c>>3, ci=c&7,
// split s=ci>>2, k-cols kc=ci&3. Each thread: row np=t>>1, 64B half h32=t&1.
__device__ __forceinline__ void issue_chunk(int c, uint32_t B_u, int np, int h32,
                                            uint32_t bxor) {
    const int nt = c >> 3, ci = c & 7;
    const int s = ci >> 2, kc = ci & 3;
    const __half* src = g_bsplit2[s] +
        ((size_t)(nt * BM + np) * DDIM + kc * 64 + h32 * 32);
    const uint32_t dst = B_u + (uint32_t)(c & 1) * BCHUNK + (uint32_t)np * 128u;
#pragma unroll
    for (int i = 0; i < 4; ++i)
        cp16(dst + (((uint32_t)(h32 * 64 + i * 16)) ^ bxor), src + i * 8);
    cp_commit();
}

// ---------------------------------------------------------------------------
// Main: 1 CTA = 128 rows vs 2048 codes. fp16 2-split, 3 passes:
// (Ah,Bh),(Al,Bh),(Ah,Bl). A splits smem-resident; B cp.async double-buffered.
// ldmatrix.x4 fragment loads; m16n8k16 HMMA, fp32 accum; fused exact argmin.
//   A layout: byte = r*512 + ((2k) ^ ((r&7)<<4))      (128 rows x 256 k)
//   B layout: byte = n*128 + ((2k') ^ ((n&7)<<4))     (128 codes x 64 k)
// ---------------------------------------------------------------------------
__global__ void __launch_bounds__(THREADS, 1)
nearest_hmma16(const float* __restrict__ x, const float* __restrict__ emb,
               float* __restrict__ out) {
    extern __shared__ __align__(16) unsigned char sm[];
    __shared__ float s_rv[2][BM];
    __shared__ int   s_rk[2][BM];
    __shared__ int   s_km[BM];

    const int t    = threadIdx.x;
    const int lane = t & 31, warp = t >> 5;
    const int g    = lane >> 2, q = lane & 3;
    const int wm   = warp & 3,  wn = warp >> 2;
    const int b    = blockIdx.x >> 3;
    const int s0   = (blockIdx.x & 7) * BM;

    const uint32_t A_u = (uint32_t)__cvta_generic_to_shared(sm);
    const uint32_t B_u = A_u + 2 * ABYTES;

    // ---- Stage A: fp16 hi/lo split of x-tile into swizzled smem ----
    const float* xb = x + ((size_t)b * DDIM) * SPATIAL + s0;
    {
        const int i = t & 127, dp = t >> 7;
#pragma unroll 4
        for (int it = 0; it < 128; ++it) {
            const int d = it * 2 + dp;
            float v = xb[(size_t)d * SPATIAL + i];
            __half hh = __float2half_rn(v);
            __half ll = __float2half_rn(v - __half2float(hh));
            uint32_t off = (uint32_t)i * 512u
                         + (((uint32_t)d * 2u) ^ (((uint32_t)(i & 7)) << 4));
            *(__half*)(sm + off)          = hh;
            *(__half*)(sm + ABYTES + off) = ll;
        }
    }

    // ---- B staging constants + prologue chunk 0 ----
    const int np = t >> 1, h32 = t & 1;
    const uint32_t bxor = ((uint32_t)(np & 7)) << 4;
    issue_chunk(0, B_u, np, h32, bxor);

    // ---- ldmatrix lane addressing ----
    const uint32_t xorv = ((uint32_t)(lane & 7)) << 4;      // same for A and B
    const int kseg = lane >> 4;                              // A: 16B k-segment
    uint32_t baseA[2];
#pragma unroll
    for (int mt = 0; mt < 2; ++mt)
        baseA[mt] = (uint32_t)(wm * 32 + mt * 16 + (lane & 15)) * 512u;
    const int nb = wn * 64 + ((lane >> 4) & 1) * 8 + (lane & 7);
    uint32_t baseB[4];
#pragma unroll
    for (int jp = 0; jp < 4; ++jp)
        baseB[jp] = (uint32_t)(nb + jp * 16) * 128u;
    const uint32_t colBk = ((uint32_t)((lane >> 3) & 1)) * 16u;

    float bv[2][2]; int bk[2][2];
#pragma unroll
    for (int mt = 0; mt < 2; ++mt)
#pragma unroll
        for (int hi = 0; hi < 2; ++hi) { bv[mt][hi] = 3.4e38f; bk[mt][hi] = 0; }

    for (int nt = 0; nt < KCODES / 128; ++nt) {
        float acc[2][8][4];
#pragma unroll
        for (int mt = 0; mt < 2; ++mt)
#pragma unroll
            for (int j = 0; j < 8; ++j)
#pragma unroll
                for (int cc = 0; cc < 4; ++cc) acc[mt][j][cc] = 0.0f;

        for (int ci = 0; ci < 8; ++ci) {
            const int c  = nt * 8 + ci;
            const int s  = ci >> 2;             // B split (0=hi, 1=lo)
            const int kc = ci & 3;
            const uint32_t bbase = B_u + (uint32_t)(c & 1) * BCHUNK;

            cp_wait0();                          // chunk c arrived
            __syncthreads();                     // visible + prev buf free
            if (c + 1 < NCHUNK) issue_chunk(c + 1, B_u, np, h32, bxor);

#pragma unroll
            for (int ks = 0; ks < 4; ++ks) {
                const uint32_t colB = ((uint32_t)ks * 32u + colBk) ^ xorv;
                uint32_t bf[8][2];
#pragma unroll
                for (int jp = 0; jp < 4; ++jp)
                    ldsm4(bf[2 * jp][0], bf[2 * jp][1],
                          bf[2 * jp + 1][0], bf[2 * jp + 1][1],
                          bbase + baseB[jp] + colB);

                const uint32_t colA =
                    ((uint32_t)(kc * 128 + ks * 32 + kseg * 16)) ^ xorv;
                // Passes with this B split: s=0 -> A hi,lo; s=1 -> A hi only.
#pragma unroll
                for (int ts = 0; ts < 2; ++ts) {
                    if (ts == 1 && s == 1) break;
                    const uint32_t abase = A_u + (uint32_t)ts * ABYTES + colA;
#pragma unroll
                    for (int mt = 0; mt < 2; ++mt) {
                        uint32_t a0, a1, a2, a3;
                        ldsm4(a0, a1, a2, a3, abase + baseA[mt]);
#pragma unroll
                        for (int j = 0; j < 8; ++j)
                            mma16816(acc[mt][j], a0, a1, a2, a3,
                                     bf[j][0], bf[j][1]);
                    }
                }
            }
        }

        // ---- n-tile epilogue: score = 0.5||e||^2 - x.e, running argmin ----
        const int kb = nt * 128 + wn * 64 + q * 2;
        float cn[16];
#pragma unroll
        for (int j = 0; j < 8; ++j) {
            cn[2 * j]     = __ldg(&g_cnorm[kb + 8 * j]);
            cn[2 * j + 1] = __ldg(&g_cnorm[kb + 8 * j + 1]);
        }
#pragma unroll
        for (int mt = 0; mt < 2; ++mt)
#pragma unroll
            for (int hi = 0; hi < 2; ++hi)
#pragma unroll
                for (int j = 0; j < 8; ++j)
#pragma unroll
                    for (int par = 0; par < 2; ++par) {
                        float v = cn[2 * j + par] - acc[mt][j][hi * 2 + par];
                        int   k = kb + 8 * j + par;
                        if (v < bv[mt][hi]) { bv[mt][hi] = v; bk[mt][hi] = k; }
                    }
    }

    // ---- Reduce: 4 q-lanes share a row; then the two wn halves ----
#pragma unroll
    for (int mt = 0; mt < 2; ++mt)
#pragma unroll
        for (int hi = 0; hi < 2; ++hi) {
            float v = bv[mt][hi]; int k = bk[mt][hi];
#pragma unroll
            for (int d = 1; d <= 2; d <<= 1) {
                float vo = __shfl_xor_sync(0xffffffffu, v, d);
                int   ko = __shfl_xor_sync(0xffffffffu, k, d);
                if (vo < v || (vo == v && ko < k)) { v = vo; k = ko; }
            }
            if (q == 0) {
                int row = wm * 32 + mt * 16 + hi * 8 + g;
                s_rv[wn][row] = v; s_rk[wn][row] = k;
            }
        }
    __syncthreads();
    if (t < BM) {
        float v0 = s_rv[0][t]; int k0 = s_rk[0][t];
        float v1 = s_rv[1][t]; int k1 = s_rk[1][t];
        s_km[t] = (v1 < v0 || (v1 == v0 && k1 < k0)) ? k1 : k0;
    }
    __syncthreads();

    // ---- Gather winning codes: out[b, d, s0+r] = emb[d, km[r]] ----
    float* ob = out + ((size_t)b * DDIM) * SPATIAL + s0;
    for (int idx = t; idx < BM * DDIM; idx += THREADS) {
        const int r = idx & (BM - 1);
        const int d = idx >> 7;
        ob[(size_t)d * SPATIAL + r] = __ldg(&emb[d * KCODES + s_km[r]]);
    }
}

// ---------------------------------------------------------------------------
extern "C" void kernel_launch(void* const* d_in, const int* in_sizes, int n_in,
                              void* d_out, int out_size) {
    const float* x   = (const float*)d_in[0];
    const float* emb = (const float*)d_in[1];
    if (n_in >= 2 && in_sizes[0] < in_sizes[1]) {   // defensive order check
        emb = (const float*)d_in[0];
        x   = (const float*)d_in[1];
    }
    float* out = (float*)d_out;

    cudaFuncSetAttribute(nearest_hmma16,
                         cudaFuncAttributeMaxDynamicSharedMemorySize, DSMEM);

    cnorm_part<<<64, 256>>>(emb);
    cnorm_combine<<<8, 256>>>();
    bsplit2_kernel<<<512, dim3(32, 8)>>>(emb);
    nearest_hmma16<<<(32 * SPATIAL) / BM, THREADS, DSMEM>>>(x, emb, out);
}

// round 13
// speedup vs baseline: 2.6788x; 1.0975x over previous
#include <cuda_runtime.h>
#include <cuda_fp16.h>
#include <cstdint>
#include <cstddef>

// Shapes: x (32,256,32,32) fp32, emb (256,2048) fp32, out = nearest codes.
#define DDIM     256
#define KCODES   2048
#define SPATIAL  1024
#define BM       128                 // rows per CTA
#define THREADS  512                 // 16 warps: 4 wm x 4 wn
#define ABYTES   65536               // one A split: 128 rows x 256 fp16
#define BCHUNK   16384               // B chunk: 128 codes x 64 fp16
#define DSMEM    (2 * ABYTES + 2 * BCHUNK)   // 163840
#define NCHUNK   128                 // 16 n-tiles x 8 chunks

// Device scratch (no allocs allowed).
__device__ float g_cnorm[KCODES];
__device__ float g_cpart[8][KCODES];
__device__ __align__(16) __half g_bsplit2[2][KCODES * DDIM];  // [split][k*256+d]

// ---------------------------------------------------------------------------
// Prep: cnorm[k] = 0.5 * sum_d emb[d][k]^2  (8-way d-parallel + combine)
// ---------------------------------------------------------------------------
__global__ void cnorm_part(const float* __restrict__ emb) {
    const int dseg = blockIdx.x >> 3;
    const int k    = (blockIdx.x & 7) * 256 + threadIdx.x;
    float s = 0.0f;
#pragma unroll
    for (int dd = 0; dd < 32; ++dd) {
        float e = emb[(dseg * 32 + dd) * KCODES + k];
        s = fmaf(e, e, s);
    }
    g_cpart[dseg][k] = s;
}
__global__ void cnorm_combine() {
    const int k = blockIdx.x * 256 + threadIdx.x;
    float s = 0.0f;
#pragma unroll
    for (int i = 0; i < 8; ++i) s += g_cpart[i][k];
    g_cnorm[k] = 0.5f * s;
}

// ---------------------------------------------------------------------------
// Prep: 2-way fp16 split of emb, transposed to [k][d] via smem tile.
// ---------------------------------------------------------------------------
__global__ void bsplit2_kernel(const float* __restrict__ emb) {
    __shared__ float tile[32][33];
    const int kt0 = (blockIdx.x & 63) * 32;
    const int dt0 = (blockIdx.x >> 6) * 32;
    const int tx = threadIdx.x, ty = threadIdx.y;
#pragma unroll
    for (int i = 0; i < 4; ++i)
        tile[ty + 8 * i][tx] = emb[(size_t)(dt0 + ty + 8 * i) * KCODES + kt0 + tx];
    __syncthreads();
#pragma unroll
    for (int i = 0; i < 4; ++i) {
        const int k = kt0 + ty + 8 * i;
        const int d = dt0 + tx;
        float v = tile[tx][ty + 8 * i];
        __half hh = __float2half_rn(v);
        __half ll = __float2half_rn(v - __half2float(hh));
        g_bsplit2[0][(size_t)k * DDIM + d] = hh;
        g_bsplit2[1][(size_t)k * DDIM + d] = ll;
    }
}

// ---------------------------------------------------------------------------
// PTX helpers (baseline sm_75/sm_80 features; compile for compute_103)
// ---------------------------------------------------------------------------
__device__ __forceinline__ void ldsm4(uint32_t& r0, uint32_t& r1, uint32_t& r2,
                                      uint32_t& r3, uint32_t addr) {
    asm volatile("ldmatrix.sync.aligned.m8n8.x4.shared.b16 {%0,%1,%2,%3}, [%4];"
                 : "=r"(r0), "=r"(r1), "=r"(r2), "=r"(r3) : "r"(addr));
}
__device__ __forceinline__ void mma16816(float* c, uint32_t a0, uint32_t a1,
                                         uint32_t a2, uint32_t a3,
                                         uint32_t b0, uint32_t b1) {
    asm volatile(
        "mma.sync.aligned.m16n8k16.row.col.f32.f16.f16.f32 "
        "{%0,%1,%2,%3}, {%4,%5,%6,%7}, {%8,%9}, {%0,%1,%2,%3};"
        : "+f"(c[0]), "+f"(c[1]), "+f"(c[2]), "+f"(c[3])
        : "r"(a0), "r"(a1), "r"(a2), "r"(a3), "r"(b0), "r"(b1));
}
__device__ __forceinline__ void cp16(uint32_t dst, const void* src) {
    asm volatile("cp.async.cg.shared.global [%0], [%1], 16;"
                 :: "r"(dst), "l"(src) : "memory");
}
__device__ __forceinline__ void cp_commit() {
    asm volatile("cp.async.commit_group;" ::: "memory");
}
__device__ __forceinline__ void cp_wait0() {
    asm volatile("cp.async.wait_group 0;" ::: "memory");
}

// Stage B chunk c into buffer (c&1). Chunk c: nt=c>>3, ci=c&7,
// split s=ci>>2, k-cols kc=ci&3. 512 threads: row np=t>>2, 32B quarter q4=t&3.
__device__ __forceinline__ void issue_chunk(int c, uint32_t B_u, int np, int q4,
                                            uint32_t bxor) {
    const int nt = c >> 3, ci = c & 7;
    const int s = ci >> 2, kc = ci & 3;
    const __half* src = g_bsplit2[s] +
        ((size_t)(nt * BM + np) * DDIM + kc * 64 + q4 * 16);
    const uint32_t dst = B_u + (uint32_t)(c & 1) * BCHUNK + (uint32_t)np * 128u;
    const uint32_t c0 = (uint32_t)q4 * 32u;
    cp16(dst + ((c0 +  0u) ^ bxor), src);
    cp16(dst + ((c0 + 16u) ^ bxor), src + 8);
    cp_commit();
}

// ---------------------------------------------------------------------------
// Main: 1 CTA = 128 rows vs 2048 codes, 512 threads (4 warps/SMSP for
// latency hiding). fp16 2-split, 3 passes: (Ah,Bh),(Al,Bh),(Ah,Bl).
// A splits smem-resident; B cp.async double-buffered; ldmatrix + m16n8k16.
//   A layout: byte = r*512 + ((2k) ^ ((r&7)<<4))      (128 rows x 256 k)
//   B layout: byte = n*128 + ((2k') ^ ((n&7)<<4))     (128 codes x 64 k)
// Warp (wm, wn): rows wm*32..+31, codes wn*32..+31 of each 128-code n-tile.
// ---------------------------------------------------------------------------
__global__ void __launch_bounds__(THREADS, 1)
nearest_hmma16(const float* __restrict__ x, const float* __restrict__ emb,
               float* __restrict__ out) {
    extern __shared__ __align__(16) unsigned char sm[];
    __shared__ float s_rv[4][BM];
    __shared__ int   s_rk[4][BM];
    __shared__ int   s_km[BM];

    const int t    = threadIdx.x;
    const int lane = t & 31, warp = t >> 5;
    const int g    = lane >> 2, q = lane & 3;
    const int wm   = warp & 3,  wn = warp >> 2;      // 4 x 4
    const int b    = blockIdx.x >> 3;
    const int s0   = (blockIdx.x & 7) * BM;

    const uint32_t A_u = (uint32_t)__cvta_generic_to_shared(sm);
    const uint32_t B_u = A_u + 2 * ABYTES;

    // ---- Stage A: fp16 hi/lo split of x-tile into swizzled smem ----
    const float* xb = x + ((size_t)b * DDIM) * SPATIAL + s0;
    {
        const int i = t & 127, dp = t >> 7;          // row, d-plane (0..3)
#pragma unroll 4
        for (int it = 0; it < 64; ++it) {
            const int d = it * 4 + dp;
            float v = xb[(size_t)d * SPATIAL + i];
            __half hh = __float2half_rn(v);
            __half ll = __float2half_rn(v - __half2float(hh));
            uint32_t off = (uint32_t)i * 512u
                         + (((uint32_t)d * 2u) ^ (((uint32_t)(i & 7)) << 4));
            *(__half*)(sm + off)          = hh;
            *(__half*)(sm + ABYTES + off) = ll;
        }
    }

    // ---- B staging constants + prologue chunk 0 ----
    const int np = t >> 2, q4 = t & 3;
    const uint32_t bxor = ((uint32_t)(np & 7)) << 4;
    issue_chunk(0, B_u, np, q4, bxor);

    // ---- ldmatrix lane addressing ----
    const uint32_t xorv = ((uint32_t)(lane & 7)) << 4;
    const int kseg = lane >> 4;                      // A: 16B k-segment
    uint32_t baseA[2];
#pragma unroll
    for (int mt = 0; mt < 2; ++mt)
        baseA[mt] = (uint32_t)(wm * 32 + mt * 16 + (lane & 15)) * 512u;
    const int nb = wn * 32 + ((lane >> 4) & 1) * 8 + (lane & 7);
    uint32_t baseB[2];
#pragma unroll
    for (int jp = 0; jp < 2; ++jp)
        baseB[jp] = (uint32_t)(nb + jp * 16) * 128u;
    const uint32_t colBk = ((uint32_t)((lane >> 3) & 1)) * 16u;

    float bv[2][2]; int bk[2][2];
#pragma unroll
    for (int mt = 0; mt < 2; ++mt)
#pragma unroll
        for (int hi = 0; hi < 2; ++hi) { bv[mt][hi] = 3.4e38f; bk[mt][hi] = 0; }

    for (int nt = 0; nt < KCODES / 128; ++nt) {
        float acc[2][4][4];
#pragma unroll
        for (int mt = 0; mt < 2; ++mt)
#pragma unroll
            for (int j = 0; j < 4; ++j)
#pragma unroll
                for (int cc = 0; cc < 4; ++cc) acc[mt][j][cc] = 0.0f;

        for (int ci = 0; ci < 8; ++ci) {
            const int c  = nt * 8 + ci;
            const int s  = ci >> 2;              // B split (0=hi, 1=lo)
            const int kc = ci & 3;
            const uint32_t bbase = B_u + (uint32_t)(c & 1) * BCHUNK;

            cp_wait0();                           // chunk c arrived
            __syncthreads();                      // visible + prev buf free
            if (c + 1 < NCHUNK) issue_chunk(c + 1, B_u, np, q4, bxor);

#pragma unroll
            for (int ks = 0; ks < 4; ++ks) {
                const uint32_t colB = ((uint32_t)ks * 32u + colBk) ^ xorv;
                uint32_t bf[4][2];
#pragma unroll
                for (int jp = 0; jp < 2; ++jp)
                    ldsm4(bf[2 * jp][0], bf[2 * jp][1],
                          bf[2 * jp + 1][0], bf[2 * jp + 1][1],
                          bbase + baseB[jp] + colB);

                const uint32_t colA =
                    ((uint32_t)(kc * 128 + ks * 32 + kseg * 16)) ^ xorv;
                // Passes with this B split: s=0 -> A hi,lo; s=1 -> A hi only.
#pragma unroll
                for (int ts = 0; ts < 2; ++ts) {
                    if (ts == 1 && s == 1) break;
                    const uint32_t abase = A_u + (uint32_t)ts * ABYTES + colA;
#pragma unroll
                    for (int mt = 0; mt < 2; ++mt) {
                        uint32_t a0, a1, a2, a3;
                        ldsm4(a0, a1, a2, a3, abase + baseA[mt]);
#pragma unroll
                        for (int j = 0; j < 4; ++j)
                            mma16816(acc[mt][j], a0, a1, a2, a3,
                                     bf[j][0], bf[j][1]);
                    }
                }
            }
        }

        // ---- n-tile epilogue: score = 0.5||e||^2 - x.e, running argmin ----
        const int kb = nt * 128 + wn * 32 + q * 2;
        float cn[8];
#pragma unroll
        for (int j = 0; j < 4; ++j) {
            cn[2 * j]     = __ldg(&g_cnorm[kb + 8 * j]);
            cn[2 * j + 1] = __ldg(&g_cnorm[kb + 8 * j + 1]);
        }
#pragma unroll
        for (int mt = 0; mt < 2; ++mt)
#pragma unroll
            for (int hi = 0; hi < 2; ++hi)
#pragma unroll
                for (int j = 0; j < 4; ++j)
#pragma unroll
                    for (int par = 0; par < 2; ++par) {
                        float v = cn[2 * j + par] - acc[mt][j][hi * 2 + par];
                        int   k = kb + 8 * j + par;
                        if (v < bv[mt][hi]) { bv[mt][hi] = v; bk[mt][hi] = k; }
                    }
    }

    // ---- Reduce: 4 q-lanes share a row; then the four wn quarters ----
#pragma unroll
    for (int mt = 0; mt < 2; ++mt)
#pragma unroll
        for (int hi = 0; hi < 2; ++hi) {
            float v = bv[mt][hi]; int k = bk[mt][hi];
#pragma unroll
            for (int d = 1; d <= 2; d <<= 1) {
                float vo = __shfl_xor_sync(0xffffffffu, v, d);
                int   ko = __shfl_xor_sync(0xffffffffu, k, d);
                if (vo < v || (vo == v && ko < k)) { v = vo; k = ko; }
            }
            if (q == 0) {
                int row = wm * 32 + mt * 16 + hi * 8 + g;
                s_rv[wn][row] = v; s_rk[wn][row] = k;
            }
        }
    __syncthreads();
    if (t < BM) {
        float bvv = s_rv[0][t]; int bkk = s_rk[0][t];
#pragma unroll
        for (int i = 1; i < 4; ++i) {
            float v = s_rv[i][t]; int k = s_rk[i][t];
            if (v < bvv || (v == bvv && k < bkk)) { bvv = v; bkk = k; }
        }
        s_km[t] = bkk;
    }
    __syncthreads();

    // ---- Gather winning codes: out[b, d, s0+r] = emb[d, km[r]] ----
    float* ob = out + ((size_t)b * DDIM) * SPATIAL + s0;
    for (int idx = t; idx < BM * DDIM; idx += THREADS) {
        const int r = idx & (BM - 1);
        const int d = idx >> 7;
        ob[(size_t)d * SPATIAL + r] = __ldg(&emb[d * KCODES + s_km[r]]);
    }
}

// ---------------------------------------------------------------------------
extern "C" void kernel_launch(void* const* d_in, const int* in_sizes, int n_in,
                              void* d_out, int out_size) {
    const float* x   = (const float*)d_in[0];
    const float* emb = (const float*)d_in[1];
    if (n_in >= 2 && in_sizes[0] < in_sizes[1]) {   // defensive order check
        emb = (const float*)d_in[0];
        x   = (const float*)d_in[1];
    }
    float* out = (float*)d_out;

    cudaFuncSetAttribute(nearest_hmma16,
                         cudaFuncAttributeMaxDynamicSharedMemorySize, DSMEM);

    cnorm_part<<<64, 256>>>(emb);
    cnorm_combine<<<8, 256>>>();
    bsplit2_kernel<<<512, dim3(32, 8)>>>(emb);
    nearest_hmma16<<<(32 * SPATIAL) / BM, THREADS, DSMEM>>>(x, emb, out);
}

// round 17
// speedup vs baseline: 2.8602x; 1.0677x over previous
#include <cuda_runtime.h>
#include <cuda_fp16.h>
#include <cstdint>
#include <cstddef>

// Shapes: x (32,256,32,32) fp32, emb (256,2048) fp32, out = nearest codes.
#define DDIM     256
#define KCODES   2048
#define SPATIAL  1024
#define BM       128                 // rows per CTA
#define THREADS  512                 // 16 warps: 4 wm x 4 wn
#define ABYTES   65536               // one A split: 128 rows x 256 fp16
#define BSTAGE   32768               // merged B chunk: 128 codes x 64 k x {hi,lo}
#define DSMEM    (2 * ABYTES + 2 * BSTAGE)   // 196608
#define NCHUNK   64                  // 16 n-tiles x 4 kc-chunks

// Device scratch (no allocs allowed).
__device__ float g_cnorm[KCODES];
__device__ float g_cpart[8][KCODES];
__device__ __align__(16) __half g_bsplit2[2][KCODES * DDIM];  // [split][k*256+d]

// ---------------------------------------------------------------------------
// Prep: cnorm[k] = 0.5 * sum_d emb[d][k]^2  (8-way d-parallel + combine)
// ---------------------------------------------------------------------------
__global__ void cnorm_part(const float* __restrict__ emb) {
    const int dseg = blockIdx.x >> 3;
    const int k    = (blockIdx.x & 7) * 256 + threadIdx.x;
    float s = 0.0f;
#pragma unroll
    for (int dd = 0; dd < 32; ++dd) {
        float e = emb[(dseg * 32 + dd) * KCODES + k];
        s = fmaf(e, e, s);
    }
    g_cpart[dseg][k] = s;
}
__global__ void cnorm_combine() {
    const int k = blockIdx.x * 256 + threadIdx.x;
    float s = 0.0f;
#pragma unroll
    for (int i = 0; i < 8; ++i) s += g_cpart[i][k];
    g_cnorm[k] = 0.5f * s;
}

// ---------------------------------------------------------------------------
// Prep: 2-way fp16 split of emb, transposed to [k][d] via smem tile.
// ---------------------------------------------------------------------------
__global__ void bsplit2_kernel(const float* __restrict__ emb) {
    __shared__ float tile[32][33];
    const int kt0 = (blockIdx.x & 63) * 32;
    const int dt0 = (blockIdx.x >> 6) * 32;
    const int tx = threadIdx.x, ty = threadIdx.y;
#pragma unroll
    for (int i = 0; i < 4; ++i)
        tile[ty + 8 * i][tx] = emb[(size_t)(dt0 + ty + 8 * i) * KCODES + kt0 + tx];
    __syncthreads();
#pragma unroll
    for (int i = 0; i < 4; ++i) {
        const int k = kt0 + ty + 8 * i;
        const int d = dt0 + tx;
        float v = tile[tx][ty + 8 * i];
        __half hh = __float2half_rn(v);
        __half ll = __float2half_rn(v - __half2float(hh));
        g_bsplit2[0][(size_t)k * DDIM + d] = hh;
        g_bsplit2[1][(size_t)k * DDIM + d] = ll;
    }
}

// ---------------------------------------------------------------------------
// PTX helpers (baseline sm_75/sm_80 features; compile for compute_103)
// ---------------------------------------------------------------------------
__device__ __forceinline__ void ldsm4(uint32_t& r0, uint32_t& r1, uint32_t& r2,
                                      uint32_t& r3, uint32_t addr) {
    asm volatile("ldmatrix.sync.aligned.m8n8.x4.shared.b16 {%0,%1,%2,%3}, [%4];"
                 : "=r"(r0), "=r"(r1), "=r"(r2), "=r"(r3) : "r"(addr));
}
__device__ __forceinline__ void mma16816(float* c, uint32_t a0, uint32_t a1,
                                         uint32_t a2, uint32_t a3,
                                         uint32_t b0, uint32_t b1) {
    asm volatile(
        "mma.sync.aligned.m16n8k16.row.col.f32.f16.f16.f32 "
        "{%0,%1,%2,%3}, {%4,%5,%6,%7}, {%8,%9}, {%0,%1,%2,%3};"
        : "+f"(c[0]), "+f"(c[1]), "+f"(c[2]), "+f"(c[3])
        : "r"(a0), "r"(a1), "r"(a2), "r"(a3), "r"(b0), "r"(b1));
}
__device__ __forceinline__ void cp16(uint32_t dst, const void* src) {
    asm volatile("cp.async.cg.shared.global [%0], [%1], 16;"
                 :: "r"(dst), "l"(src) : "memory");
}
__device__ __forceinline__ void cp_commit() {
    asm volatile("cp.async.commit_group;" ::: "memory");
}
__device__ __forceinline__ void cp_wait0() {
    asm volatile("cp.async.wait_group 0;" ::: "memory");
}

// Stage merged B chunk c (both fp16 splits of one kc) into buffer (c&1).
// Chunk c: nt = c>>2, kc = c&3.  512 threads: row np=t>>2, 16B quarter q4=t&3.
// Layout inside a stage: [hi 16KB][lo 16KB], each n*128 + ((2k')^((n&7)<<4)).
__device__ __forceinline__ void issue_chunk(int c, uint32_t B_u, int np, int q4,
                                            uint32_t bxor) {
    const int nt = c >> 2, kc = c & 3;
    const size_t soff = (size_t)(nt * BM + np) * DDIM + kc * 64 + q4 * 16;
    const uint32_t dst = B_u + (uint32_t)(c & 1) * BSTAGE + (uint32_t)np * 128u;
    const uint32_t c0 = (uint32_t)q4 * 32u;
    const __half* sh = g_bsplit2[0] + soff;
    const __half* sl = g_bsplit2[1] + soff;
    cp16(dst + ((c0 +  0u) ^ bxor),          sh);
    cp16(dst + ((c0 + 16u) ^ bxor),          sh + 8);
    cp16(dst + 16384u + ((c0 +  0u) ^ bxor), sl);
    cp16(dst + 16384u + ((c0 + 16u) ^ bxor), sl + 8);
    cp_commit();
}

// ---------------------------------------------------------------------------
// Main: 1 CTA = 128 rows vs 2048 codes, 512 threads. fp16 2-split, 3 passes
// (Ah.Bh, Al.Bh, Ah.Bl) with MERGED hi+lo B chunks so each (kc,ks) loads its
// A fragments ONCE: 8 ldsm.x4 -> 24 HMMA (171 B smem per MMA vs 213 before),
// and half the chunk barriers (64 vs 128).
//   A layout: byte = r*512 + ((2k) ^ ((r&7)<<4))      (128 rows x 256 k)
//   B layout: byte = n*128 + ((2k') ^ ((n&7)<<4))     (128 codes x 64 k)
// Warp (wm, wn): rows wm*32..+31, codes wn*32..+31 of each 128-code n-tile.
// ---------------------------------------------------------------------------
__global__ void __launch_bounds__(THREADS, 1)
nearest_hmma16(const float* __restrict__ x, const float* __restrict__ emb,
               float* __restrict__ out) {
    extern __shared__ __align__(16) unsigned char sm[];
    __shared__ float s_rv[4][BM];
    __shared__ int   s_rk[4][BM];
    __shared__ int   s_km[BM];

    const int t    = threadIdx.x;
    const int lane = t & 31, warp = t >> 5;
    const int g    = lane >> 2, q = lane & 3;
    const int wm   = warp & 3,  wn = warp >> 2;      // 4 x 4
    const int b    = blockIdx.x >> 3;
    const int s0   = (blockIdx.x & 7) * BM;

    const uint32_t A_u = (uint32_t)__cvta_generic_to_shared(sm);
    const uint32_t B_u = A_u + 2 * ABYTES;

    // ---- Stage A: fp16 hi/lo split of x-tile into swizzled smem ----
    const float* xb = x + ((size_t)b * DDIM) * SPATIAL + s0;
    {
        const int i = t & 127, dp = t >> 7;          // row, d-plane (0..3)
#pragma unroll 4
        for (int it = 0; it < 64; ++it) {
            const int d = it * 4 + dp;
            float v = xb[(size_t)d * SPATIAL + i];
            __half hh = __float2half_rn(v);
            __half ll = __float2half_rn(v - __half2float(hh));
            uint32_t off = (uint32_t)i * 512u
                         + (((uint32_t)d * 2u) ^ (((uint32_t)(i & 7)) << 4));
            *(__half*)(sm + off)          = hh;
            *(__half*)(sm + ABYTES + off) = ll;
        }
    }

    // ---- B staging constants + prologue chunk 0 ----
    const int np = t >> 2, q4 = t & 3;
    const uint32_t bxor = ((uint32_t)(np & 7)) << 4;
    issue_chunk(0, B_u, np, q4, bxor);

    // ---- ldmatrix lane addressing ----
    const uint32_t xorv = ((uint32_t)(lane & 7)) << 4;
    const int kseg = lane >> 4;                      // A: 16B k-segment
    uint32_t baseA[2];
#pragma unroll
    for (int mt = 0; mt < 2; ++mt)
        baseA[mt] = (uint32_t)(wm * 32 + mt * 16 + (lane & 15)) * 512u;
    const int nb = wn * 32 + ((lane >> 4) & 1) * 8 + (lane & 7);
    uint32_t baseB[2];
#pragma unroll
    for (int jp = 0; jp < 2; ++jp)
        baseB[jp] = (uint32_t)(nb + jp * 16) * 128u;
    const uint32_t colBk = ((uint32_t)((lane >> 3) & 1)) * 16u;

    float bv[2][2]; int bk[2][2];
#pragma unroll
    for (int mt = 0; mt < 2; ++mt)
#pragma unroll
        for (int hi = 0; hi < 2; ++hi) { bv[mt][hi] = 3.4e38f; bk[mt][hi] = 0; }

    for (int nt = 0; nt < KCODES / 128; ++nt) {
        float acc[2][4][4];
#pragma unroll
        for (int mt = 0; mt < 2; ++mt)
#pragma unroll
            for (int j = 0; j < 4; ++j)
#pragma unroll
                for (int cc = 0; cc < 4; ++cc) acc[mt][j][cc] = 0.0f;

        for (int kci = 0; kci < 4; ++kci) {
            const int c = nt * 4 + kci;
            const uint32_t bbase = B_u + (uint32_t)(c & 1) * BSTAGE;

            cp_wait0();                           // chunk c arrived
            __syncthreads();                      // visible + prev buf free
            if (c + 1 < NCHUNK) issue_chunk(c + 1, B_u, np, q4, bxor);

#pragma unroll
            for (int ks = 0; ks < 4; ++ks) {
                const uint32_t colB = ((uint32_t)ks * 32u + colBk) ^ xorv;
                const uint32_t colA =
                    ((uint32_t)(kci * 128 + ks * 32 + kseg * 16)) ^ xorv;

                // 8 independent ldsm.x4 issued up front: Bh, Bl, Ah, Al.
                uint32_t bh[4][2], bl[4][2], ah[2][4], al[2][4];
#pragma unroll
                for (int jp = 0; jp < 2; ++jp) {
                    ldsm4(bh[2 * jp][0], bh[2 * jp][1],
                          bh[2 * jp + 1][0], bh[2 * jp + 1][1],
                          bbase + baseB[jp] + colB);
                    ldsm4(bl[2 * jp][0], bl[2 * jp][1],
                          bl[2 * jp + 1][0], bl[2 * jp + 1][1],
                          bbase + 16384u + baseB[jp] + colB);
                }
#pragma unroll
                for (int mt = 0; mt < 2; ++mt) {
                    ldsm4(ah[mt][0], ah[mt][1], ah[mt][2], ah[mt][3],
                          A_u + baseA[mt] + colA);
                    ldsm4(al[mt][0], al[mt][1], al[mt][2], al[mt][3],
                          A_u + ABYTES + baseA[mt] + colA);
                }

                // 24 HMMA: Ah.Bh + Al.Bh + Ah.Bl into one fp32 accumulator.
#pragma unroll
                for (int mt = 0; mt < 2; ++mt)
#pragma unroll
                    for (int j = 0; j < 4; ++j)
                        mma16816(acc[mt][j], ah[mt][0], ah[mt][1],
                                 ah[mt][2], ah[mt][3], bh[j][0], bh[j][1]);
#pragma unroll
                for (int mt = 0; mt < 2; ++mt)
#pragma unroll
                    for (int j = 0; j < 4; ++j)
                        mma16816(acc[mt][j], al[mt][0], al[mt][1],
                                 al[mt][2], al[mt][3], bh[j][0], bh[j][1]);
#pragma unroll
                for (int mt = 0; mt < 2; ++mt)
#pragma unroll
                    for (int j = 0; j < 4; ++j)
                        mma16816(acc[mt][j], ah[mt][0], ah[mt][1],
                                 ah[mt][2], ah[mt][3], bl[j][0], bl[j][1]);
            }
        }

        // ---- n-tile epilogue: score = 0.5||e||^2 - x.e, running argmin ----
        const int kb = nt * 128 + wn * 32 + q * 2;
        float cn[8];
#pragma unroll
        for (int j = 0; j < 4; ++j) {
            cn[2 * j]     = __ldg(&g_cnorm[kb + 8 * j]);
            cn[2 * j + 1] = __ldg(&g_cnorm[kb + 8 * j + 1]);
        }
#pragma unroll
        for (int mt = 0; mt < 2; ++mt)
#pragma unroll
            for (int hi = 0; hi < 2; ++hi)
#pragma unroll
                for (int j = 0; j < 4; ++j)
#pragma unroll
                    for (int par = 0; par < 2; ++par) {
                        float v = cn[2 * j + par] - acc[mt][j][hi * 2 + par];
                        int   k = kb + 8 * j + par;
                        if (v < bv[mt][hi]) { bv[mt][hi] = v; bk[mt][hi] = k; }
                    }
    }

    // ---- Reduce: 4 q-lanes share a row; then the four wn quarters ----
#pragma unroll
    for (int mt = 0; mt < 2; ++mt)
#pragma unroll
        for (int hi = 0; hi < 2; ++hi) {
            float v = bv[mt][hi]; int k = bk[mt][hi];
#pragma unroll
            for (int d = 1; d <= 2; d <<= 1) {
                float vo = __shfl_xor_sync(0xffffffffu, v, d);
                int   ko = __shfl_xor_sync(0xffffffffu, k, d);
                if (vo < v || (vo == v && ko < k)) { v = vo; k = ko; }
            }
            if (q == 0) {
                int row = wm * 32 + mt * 16 + hi * 8 + g;
                s_rv[wn][row] = v; s_rk[wn][row] = k;
            }
        }
    __syncthreads();
    if (t < BM) {
        float bvv = s_rv[0][t]; int bkk = s_rk[0][t];
#pragma unroll
        for (int i = 1; i < 4; ++i) {
            float v = s_rv[i][t]; int k = s_rk[i][t];
            if (v < bvv || (v == bvv && k < bkk)) { bvv = v; bkk = k; }
        }
        s_km[t] = bkk;
    }
    __syncthreads();

    // ---- Gather winning codes: out[b, d, s0+r] = emb[d, km[r]] ----
    float* ob = out + ((size_t)b * DDIM) * SPATIAL + s0;
    for (int idx = t; idx < BM * DDIM; idx += THREADS) {
        const int r = idx & (BM - 1);
        const int d = idx >> 7;
        ob[(size_t)d * SPATIAL + r] = __ldg(&emb[d * KCODES + s_km[r]]);
    }
}

// ---------------------------------------------------------------------------
extern "C" void kernel_launch(void* const* d_in, const int* in_sizes, int n_in,
                              void* d_out, int out_size) {
    const float* x   = (const float*)d_in[0];
    const float* emb = (const float*)d_in[1];
    if (n_in >= 2 && in_sizes[0] < in_sizes[1]) {   // defensive order check
        emb = (const float*)d_in[0];
        x   = (const float*)d_in[1];
    }
    float* out = (float*)d_out;

    cudaFuncSetAttribute(nearest_hmma16,
                         cudaFuncAttributeMaxDynamicSharedMemorySize, DSMEM);

    cnorm_part<<<64, 256>>>(emb);
    cnorm_combine<<<8, 256>>>();
    bsplit2_kernel<<<512, dim3(32, 8)>>>(emb);
    nearest_hmma16<<<(32 * SPATIAL) / BM, THREADS, DSMEM>>>(x, emb, out);
}